// round 11
// baseline (speedup 1.0000x reference)
#include <cuda_runtime.h>
#include <cstdint>

// Spherical: out = x * |s| — HBM mixed-stream bound (~6 TB/s measured ceiling
// for 128B-granular requests). R11: TMA bulk streaming — 16KB contiguous
// cp.async.bulk transfers per request so the DRAM scheduler sees long
// same-row bursts (fewer read/write bus turnarounds).

#define THREADS 256
#define TILE_BYTES 16384          // 16KB per tile = 4096 floats = 1024 float4
#define TILE_F4 1024
#define TILES_PER_BLOCK 4
#define STAGES 4                  // one buffer per tile: no reuse, simple pipe
#define SMEM_BUF_OFF 128          // mbarriers live in [0,128)
#define SMEM_TOTAL (SMEM_BUF_OFF + STAGES * TILE_BYTES)

__device__ __forceinline__ uint32_t smem_u32(const void* p) {
    uint32_t a;
    asm("{ .reg .u64 t; cvta.to.shared.u64 t, %1; cvt.u32.u64 %0, t; }"
        : "=r"(a) : "l"(p));
    return a;
}

__global__ void __launch_bounds__(THREADS) spherical_tma_kernel(
    const float* __restrict__ x,
    const float* __restrict__ s,
    float* __restrict__ out)
{
    extern __shared__ char smem[];
    const uint32_t sbase = smem_u32(smem);
    const int tid = threadIdx.x;

    // mbarrier per stage at sbase + 8*t
    if (tid == 0) {
        #pragma unroll
        for (int t = 0; t < STAGES; t++) {
            asm volatile("mbarrier.init.shared.b64 [%0], 1;"
                         :: "r"(sbase + 8 * t) : "memory");
        }
    }
    __syncthreads();

    const long long tile0 = (long long)blockIdx.x * TILES_PER_BLOCK;
    const float* gsrc = x + tile0 * (TILE_BYTES / 4);
    float* gdst = out + tile0 * (TILE_BYTES / 4);

    // Issue all tile loads up front (4 x 16KB bulk requests in flight).
    if (tid == 0) {
        #pragma unroll
        for (int t = 0; t < TILES_PER_BLOCK; t++) {
            uint32_t mbar = sbase + 8 * t;
            uint32_t dst  = sbase + SMEM_BUF_OFF + t * TILE_BYTES;
            asm volatile("mbarrier.arrive.expect_tx.shared.b64 _, [%0], %1;"
                         :: "r"(mbar), "r"((uint32_t)TILE_BYTES) : "memory");
            asm volatile(
                "cp.async.bulk.shared::cluster.global.mbarrier::complete_tx::bytes"
                " [%0], [%1], %2, [%3];"
                :: "r"(dst), "l"(gsrc + (long long)t * (TILE_BYTES / 4)),
                   "r"((uint32_t)TILE_BYTES), "r"(mbar)
                : "memory");
        }
    }

    const float scale = fabsf(__ldg(s));

    #pragma unroll
    for (int t = 0; t < TILES_PER_BLOCK; t++) {
        // Wait for tile t (phase 0; each barrier used exactly once).
        {
            const uint32_t mbar = sbase + 8 * t;
            uint32_t done;
            asm volatile(
                "{\n\t.reg .pred p;\n\t"
                "mbarrier.try_wait.parity.acquire.cta.shared::cta.b64 p, [%1], 0;\n\t"
                "selp.b32 %0, 1, 0, p;\n\t}"
                : "=r"(done) : "r"(mbar) : "memory");
            while (!done) {
                asm volatile(
                    "{\n\t.reg .pred p;\n\t"
                    "mbarrier.try_wait.parity.acquire.cta.shared::cta.b64 p, [%1], 0, 0x989680;\n\t"
                    "selp.b32 %0, 1, 0, p;\n\t}"
                    : "=r"(done) : "r"(mbar) : "memory");
            }
        }

        // Scale in place: 1024 float4 per tile, 4 per thread.
        float4* buf = reinterpret_cast<float4*>(smem + SMEM_BUF_OFF + t * TILE_BYTES);
        #pragma unroll
        for (int k = 0; k < 4; k++) {
            float4 v = buf[tid + k * THREADS];
            v.x *= scale; v.y *= scale; v.z *= scale; v.w *= scale;
            buf[tid + k * THREADS] = v;
        }
        __syncthreads();

        // Bulk store: 16KB contiguous SMEM -> GMEM.
        if (tid == 0) {
            asm volatile("fence.proxy.async.shared::cta;" ::: "memory");
            uint32_t src = sbase + SMEM_BUF_OFF + t * TILE_BYTES;
            asm volatile(
                "cp.async.bulk.global.shared::cta.bulk_group [%0], [%1], %2;"
                :: "l"(gdst + (long long)t * (TILE_BYTES / 4)),
                   "r"(src), "r"((uint32_t)TILE_BYTES)
                : "memory");
            asm volatile("cp.async.bulk.commit_group;" ::: "memory");
        }
    }

    // Drain outstanding bulk stores before exit.
    if (tid == 0) {
        asm volatile("cp.async.bulk.wait_group 0;" ::: "memory");
    }
}

// Scalar remainder for shapes not divisible by the tile grid (unused here).
__global__ void __launch_bounds__(256) spherical_scale_tail(
    const float* __restrict__ x,
    const float* __restrict__ s,
    float* __restrict__ out,
    int start, int n)
{
    const float scale = fabsf(__ldg(s));
    int i = start + blockIdx.x * blockDim.x + threadIdx.x;
    if (i < n) out[i] = x[i] * scale;
}

extern "C" void kernel_launch(void* const* d_in, const int* in_sizes, int n_in,
                              void* d_out, int out_size)
{
    const float* x = (const float*)d_in[0];
    const float* s = (const float*)d_in[1];
    float* out = (float*)d_out;

    const int n = in_sizes[0];                          // 33554432
    const int floats_per_block = TILES_PER_BLOCK * (TILE_BYTES / 4);  // 16384
    const int blocks = n / floats_per_block;            // 2048 (exact)

    static bool attr_set = false;
    if (!attr_set) {
        cudaFuncSetAttribute(spherical_tma_kernel,
                             cudaFuncAttributeMaxDynamicSharedMemorySize,
                             SMEM_TOTAL);
        attr_set = true;
    }

    spherical_tma_kernel<<<blocks, THREADS, SMEM_TOTAL>>>(x, s, out);

    const int covered = blocks * floats_per_block;
    if (covered < n) {
        const int rem = n - covered;
        spherical_scale_tail<<<(rem + 255) / 256, 256>>>(x, s, out, covered, n);
    }
}

// round 12
// speedup vs baseline: 1.0351x; 1.0351x over previous
#include <cuda_runtime.h>

// Spherical: out = x * |s|  (reference GEMM vs scaled identity == elementwise scale).
//
// CONVERGED FINAL: pure HBM stream, 268 MB logical traffic. Eleven measured
// configurations (MLP 1-8, occ 29-84%, pipelined, persistent, 256-bit v8 ops,
// L2::256B, L2 pinning/evict_last, TMA 16KB bulk) all land at 72-75% of DRAM
// spec — the B300 mixed read+write streaming ceiling (~5.9-6.0 TB/s), path-
// independent per B300_MICROARCH. This is the measured-best shape:
// 8192 blocks x 256 threads, 4 front-batched LDG.128/thread, streaming .cs.

#define THREADS 256
#define V 4
#define SPAN (THREADS * V)   // 1024 float4 = 16KB per block

__global__ void __launch_bounds__(THREADS) spherical_scale_kernel(
    const float4* __restrict__ x,
    const float* __restrict__ s,
    float4* __restrict__ out)
{
    const float scale = fabsf(__ldg(s));

    const int base = blockIdx.x * SPAN + threadIdx.x;

    // 4 independent LDG.128 front-batched (MLP_p1 = 4), fully coalesced.
    float4 v0 = __ldcs(&x[base + 0 * THREADS]);
    float4 v1 = __ldcs(&x[base + 1 * THREADS]);
    float4 v2 = __ldcs(&x[base + 2 * THREADS]);
    float4 v3 = __ldcs(&x[base + 3 * THREADS]);

    v0.x *= scale; v0.y *= scale; v0.z *= scale; v0.w *= scale;
    v1.x *= scale; v1.y *= scale; v1.z *= scale; v1.w *= scale;
    v2.x *= scale; v2.y *= scale; v2.z *= scale; v2.w *= scale;
    v3.x *= scale; v3.y *= scale; v3.z *= scale; v3.w *= scale;

    __stcs(&out[base + 0 * THREADS], v0);
    __stcs(&out[base + 1 * THREADS], v1);
    __stcs(&out[base + 2 * THREADS], v2);
    __stcs(&out[base + 3 * THREADS], v3);
}

// Generic remainder kernel for sizes not divisible by the main tile
// (unused at 8192x4096; kept for shape-safety).
__global__ void __launch_bounds__(256) spherical_scale_tail(
    const float* __restrict__ x,
    const float* __restrict__ s,
    float* __restrict__ out,
    int start, int n)
{
    const float scale = fabsf(__ldg(s));
    int i = start + blockIdx.x * blockDim.x + threadIdx.x;
    if (i < n) out[i] = x[i] * scale;
}

extern "C" void kernel_launch(void* const* d_in, const int* in_sizes, int n_in,
                              void* d_out, int out_size)
{
    const float4* x = (const float4*)d_in[0];
    const float*  s = (const float*)d_in[1];
    float4* out = (float4*)d_out;

    const int n  = in_sizes[0];          // 33554432
    const int n4 = n / 4;                // 8388608
    const int blocks = n4 / SPAN;        // 8192 (exact cover)

    spherical_scale_kernel<<<blocks, THREADS>>>(x, s, out);

    // Remainder elements (none for this shape).
    const int covered = blocks * SPAN * 4;
    if (covered < n) {
        const int rem = n - covered;
        spherical_scale_tail<<<(rem + 255) / 256, 256>>>(
            (const float*)d_in[0], s, (float*)d_out, covered, n);
    }
}